// round 5
// baseline (speedup 1.0000x reference)
#include <cuda_runtime.h>
#include <math.h>

// ContrastiveLoss: B=4096, D=256, L=3
// loss = sum_{i<j} [0.5*same*dist + 0.5*(1-same)*max(R-dist,0)] / B
// Strategy: sq-norm + packed-label prep kernel, then a 128x128-tiled
// SGEMM-style pairwise kernel over upper-triangle blocks with fused epilogue.
// NOTE: labels arrive as int32 (JAX downcasts int64 with x64 disabled).

#define RADIUS_F 1.0f
#define MAXB 4096
#define BM 128
#define BN 128
#define BK 16
#define TM 8
#define TN 8

__device__ float g_sq[MAXB];
__device__ int   g_lab[MAXB];

__global__ void cl_init_out(float* out) { out[0] = 0.0f; }

// One warp per row: squared norm + pack 3 labels (each in [0,8)) into 9 bits.
__global__ void cl_prep(const float* __restrict__ f,
                        const int* __restrict__ lab,   // int32! (JAX x64 off)
                        int B, int D) {
    int gwarp = (blockIdx.x * blockDim.x + threadIdx.x) >> 5;
    int lane  = threadIdx.x & 31;
    if (gwarp >= B) return;
    const float* row = f + (size_t)gwarp * D;
    float s = 0.0f;
    for (int k = lane; k < D; k += 32) {
        float v = row[k];
        s = fmaf(v, v, s);
    }
    #pragma unroll
    for (int o = 16; o; o >>= 1) s += __shfl_xor_sync(0xffffffffu, s, o);
    if (lane == 0) {
        g_sq[gwarp] = s;
        int l0 = lab[gwarp * 3 + 0];
        int l1 = lab[gwarp * 3 + 1];
        int l2 = lab[gwarp * 3 + 2];
        g_lab[gwarp] = l0 | (l1 << 3) | (l2 << 6);
    }
}

__global__ __launch_bounds__(256, 2)
void cl_pair(const float* __restrict__ f, float* __restrict__ out,
             int B, int D) {
    const int bj = blockIdx.x;   // column tile
    const int bi = blockIdx.y;   // row tile
    if (bi > bj) return;         // strict upper triangle at tile granularity

    __shared__ float As[BK][BM];
    __shared__ float Bs[BK][BN];

    const int tid = threadIdx.x;
    const int tm  = (tid >> 4) * TM;   // 0..120
    const int tn  = (tid & 15) * TN;   // 0..120

    const float* Abase = f + (size_t)(bi * BM) * D;
    const float* Bbase = f + (size_t)(bj * BN) * D;

    float acc[TM][TN];
    #pragma unroll
    for (int a = 0; a < TM; a++)
        #pragma unroll
        for (int b = 0; b < TN; b++) acc[a][b] = 0.0f;

    for (int k0 = 0; k0 < D; k0 += BK) {
        // Cooperative load of 128x16 A and B tiles, transposed into [k][m].
        #pragma unroll
        for (int j = 0; j < 2; j++) {
            int slot = tid + j * 256;       // 0..511
            int row  = slot >> 2;           // 0..127
            int kv   = (slot & 3) * 4;      // 0,4,8,12
            float4 va = *reinterpret_cast<const float4*>(Abase + (size_t)row * D + k0 + kv);
            float4 vb = *reinterpret_cast<const float4*>(Bbase + (size_t)row * D + k0 + kv);
            As[kv + 0][row] = va.x; As[kv + 1][row] = va.y;
            As[kv + 2][row] = va.z; As[kv + 3][row] = va.w;
            Bs[kv + 0][row] = vb.x; Bs[kv + 1][row] = vb.y;
            Bs[kv + 2][row] = vb.z; Bs[kv + 3][row] = vb.w;
        }
        __syncthreads();

        #pragma unroll
        for (int k = 0; k < BK; k++) {
            float rm[TM], rn[TN];
            #pragma unroll
            for (int a = 0; a < TM; a++) rm[a] = As[k][tm + a];
            #pragma unroll
            for (int b = 0; b < TN; b++) rn[b] = Bs[k][tn + b];
            #pragma unroll
            for (int a = 0; a < TM; a++)
                #pragma unroll
                for (int b = 0; b < TN; b++)
                    acc[a][b] = fmaf(rm[a], rn[b], acc[a][b]);
        }
        __syncthreads();
    }

    // Fused epilogue: distances + contrastive term + local reduction.
    const int i0 = bi * BM + tm;
    const int j0 = bj * BN + tn;

    float sqi[TM], sqj[TN];
    int   li[TM],  lj[TN];
    #pragma unroll
    for (int a = 0; a < TM; a++) { sqi[a] = g_sq[i0 + a]; li[a] = g_lab[i0 + a]; }
    #pragma unroll
    for (int b = 0; b < TN; b++) { sqj[b] = g_sq[j0 + b]; lj[b] = g_lab[j0 + b]; }

    float lsum = 0.0f;
    #pragma unroll
    for (int a = 0; a < TM; a++) {
        #pragma unroll
        for (int b = 0; b < TN; b++) {
            int i = i0 + a, j = j0 + b;
            if (i < j) {
                float d2 = fmaxf(sqi[a] + sqj[b] - 2.0f * acc[a][b], 0.0f);
                if (li[a] == lj[b]) {
                    // same-label pair: 0.5 * dist  (prob 1/512 -> sqrt predicated)
                    lsum += 0.5f * sqrtf(d2);
                } else if (d2 < RADIUS_F * RADIUS_F) {
                    // hinge active only if dist < 1 (essentially never for this data)
                    lsum += 0.5f * (RADIUS_F - sqrtf(d2));
                }
            }
        }
    }

    // Block reduction
    __shared__ float red[256];
    red[tid] = lsum;
    __syncthreads();
    #pragma unroll
    for (int s = 128; s; s >>= 1) {
        if (tid < s) red[tid] += red[tid + s];
        __syncthreads();
    }
    if (tid == 0) atomicAdd(out, red[0] * (1.0f / (float)B));
}

extern "C" void kernel_launch(void* const* d_in, const int* in_sizes, int n_in,
                              void* d_out, int out_size) {
    const float* f   = (const float*)d_in[0];
    const int*   lab = (const int*)d_in[1];    // int32 labels
    float*       out = (float*)d_out;

    int B = in_sizes[1] / 3;        // labels: [B,3]
    int D = in_sizes[0] / B;        // features: [B,D]

    cl_init_out<<<1, 1>>>(out);
    cl_prep<<<(B * 32 + 255) / 256, 256>>>(f, lab, B, D);

    dim3 grid(B / BN, B / BM);
    cl_pair<<<grid, 256>>>(f, out, B, D);
}

// round 11
// speedup vs baseline: 3.4511x; 3.4511x over previous
#include <cuda_runtime.h>
#include <cuda_bf16.h>
#include <math.h>
#include <stdint.h>

// ContrastiveLoss B=4096, D=256, L=3.
// Portable tensor-core path: bf16 Gram via ldmatrix + mma.sync m16n8k16
// (sm_80 PTX encodings — the harness toolchain lowers through compute_103,
// which rejects tcgen05). Register accumulators, fused distance epilogue.

#define RADIUS_F 1.0f
#define MAXB  4096
#define DFEAT 256
#define BM 128
#define BN 128
#define BK 32

__device__ float g_sq[MAXB];
__device__ int   g_lab[MAXB];
__device__ __align__(1024) __nv_bfloat16 g_fb[MAXB * DFEAT];  // row-major bf16

__global__ void cl_init_out(float* out) { out[0] = 0.0f; }

// one warp per row: exact fp32 norm, packed labels, bf16 row store
__global__ void cl_prep(const float* __restrict__ f, const int* __restrict__ lab, int B) {
    int row  = (blockIdx.x * blockDim.x + threadIdx.x) >> 5;
    int lane = threadIdx.x & 31;
    if (row >= B) return;
    const float* r = f + (size_t)row * DFEAT;

    float4 v0 = *reinterpret_cast<const float4*>(r + lane * 8);
    float4 v1 = *reinterpret_cast<const float4*>(r + lane * 8 + 4);
    float s = 0.0f;
    s = fmaf(v0.x, v0.x, s); s = fmaf(v0.y, v0.y, s);
    s = fmaf(v0.z, v0.z, s); s = fmaf(v0.w, v0.w, s);
    s = fmaf(v1.x, v1.x, s); s = fmaf(v1.y, v1.y, s);
    s = fmaf(v1.z, v1.z, s); s = fmaf(v1.w, v1.w, s);
    #pragma unroll
    for (int o = 16; o; o >>= 1) s += __shfl_xor_sync(0xffffffffu, s, o);
    if (lane == 0) {
        g_sq[row]  = s;
        g_lab[row] = lab[row * 3 + 0] | (lab[row * 3 + 1] << 3) | (lab[row * 3 + 2] << 6);
    }

    __nv_bfloat162 b0 = __float22bfloat162_rn(make_float2(v0.x, v0.y));
    __nv_bfloat162 b1 = __float22bfloat162_rn(make_float2(v0.z, v0.w));
    __nv_bfloat162 b2 = __float22bfloat162_rn(make_float2(v1.x, v1.y));
    __nv_bfloat162 b3 = __float22bfloat162_rn(make_float2(v1.z, v1.w));
    uint4 pk;
    pk.x = *reinterpret_cast<uint32_t*>(&b0);
    pk.y = *reinterpret_cast<uint32_t*>(&b1);
    pk.z = *reinterpret_cast<uint32_t*>(&b2);
    pk.w = *reinterpret_cast<uint32_t*>(&b3);
    *reinterpret_cast<uint4*>(g_fb + (size_t)row * DFEAT + lane * 8) = pk;
}

// ---- helpers ----
__device__ __forceinline__ uint32_t smem_u32(const void* p) {
    uint32_t a;
    asm("{ .reg .u64 t; cvta.to.shared.u64 t, %1; cvt.u32.u64 %0, t; }" : "=r"(a) : "l"(p));
    return a;
}
// tile row = 64 bytes (32 bf16) = 4x 16B chunks; XOR rotate chunks by (row>>1)&3
__device__ __forceinline__ uint32_t swoff(int row, int chunk) {
    return (uint32_t)(row * 64 + (((chunk) ^ ((row >> 1) & 3)) << 4));
}
#define CP_ASYNC16(smem, gptr) \
    asm volatile("cp.async.ca.shared.global [%0], [%1], 16;" :: "r"(smem), "l"(gptr) : "memory")
#define CP_COMMIT() asm volatile("cp.async.commit_group;" ::: "memory")
#define CP_WAIT(n)  asm volatile("cp.async.wait_group %0;" :: "n"(n) : "memory")
#define LDM_X4(r0, r1, r2, r3, a) \
    asm volatile("ldmatrix.sync.aligned.m8n8.x4.shared.b16 {%0,%1,%2,%3}, [%4];" \
                 : "=r"(r0), "=r"(r1), "=r"(r2), "=r"(r3) : "r"(a))
#define MMA16816(c, A, b0, b1) \
    asm volatile("mma.sync.aligned.m16n8k16.row.col.f32.bf16.bf16.f32 " \
                 "{%0,%1,%2,%3}, {%4,%5,%6,%7}, {%8,%9}, {%0,%1,%2,%3};" \
                 : "+f"((c)[0]), "+f"((c)[1]), "+f"((c)[2]), "+f"((c)[3]) \
                 : "r"((A)[0]), "r"((A)[1]), "r"((A)[2]), "r"((A)[3]), "r"(b0), "r"(b1))

#define TILE_BYTES (128 * 64)   // 8KB per operand tile

__global__ __launch_bounds__(256, 2)
void cl_pair_mma(float* __restrict__ out, int B) {
    const int bj = blockIdx.x, bi = blockIdx.y;
    if (bi > bj) return;

    __shared__ __align__(16) char sm_t[2][2][TILE_BYTES];  // [stage][op] 32KB
    __shared__ float s_sqj[BN];
    __shared__ int   s_labj[BN];

    const int tid    = threadIdx.x;
    const int lane   = tid & 31;
    const int wid    = tid >> 5;
    const int warp_m = wid & 3;   // 4 warps along M (32 rows each)
    const int warp_n = wid >> 2;  // 2 warps along N (64 cols each)
    const int i0 = bi * BM, j0 = bj * BN;

    if (tid < BN) {
        s_sqj[tid]  = g_sq[j0 + tid];
        s_labj[tid] = g_lab[j0 + tid];
    }

    const char* gA = reinterpret_cast<const char*>(g_fb + (size_t)i0 * DFEAT);
    const char* gB = reinterpret_cast<const char*>(g_fb + (size_t)j0 * DFEAT);
    const uint32_t smA[2] = { smem_u32(sm_t[0][0]), smem_u32(sm_t[1][0]) };
    const uint32_t smB[2] = { smem_u32(sm_t[0][1]), smem_u32(sm_t[1][1]) };

    // loader mapping: 512 16B-chunks per operand; 2 per thread per operand
    const int lrow0 = tid >> 1;                 // rows 0..127
    const int lch0  = (tid & 1) * 2;            // chunks {0,1} or {2,3}

    auto load_stage = [&](int st, int k0) {
        #pragma unroll
        for (int c = 0; c < 2; c++) {
            int row = lrow0, ch = lch0 + c;
            const char* ga = gA + (size_t)row * (DFEAT * 2) + k0 * 2 + ch * 16;
            const char* gb = gB + (size_t)row * (DFEAT * 2) + k0 * 2 + ch * 16;
            CP_ASYNC16(smA[st] + swoff(row, ch), ga);
            CP_ASYNC16(smB[st] + swoff(row, ch), gb);
        }
    };

    float acc[2][8][4];
    #pragma unroll
    for (int mt = 0; mt < 2; mt++)
        #pragma unroll
        for (int nt = 0; nt < 8; nt++)
            #pragma unroll
            for (int e = 0; e < 4; e++) acc[mt][nt][e] = 0.0f;

    load_stage(0, 0);
    CP_COMMIT();

    // ldmatrix lane roles (constant across k)
    const int a_row = warp_m * 32 + (lane & 15);      // + mt*16
    const int a_chb = (lane >> 4);                    // chunk base 0/1
    const int b_row = warp_n * 64 + (lane & 7) + ((lane & 16) >> 1);  // + p*16
    const int b_chb = (lane >> 3) & 1;

    const int NK = DFEAT / BK;   // 8
    for (int kt = 0; kt < NK; kt++) {
        const int st = kt & 1;
        if (kt + 1 < NK) {
            load_stage(st ^ 1, (kt + 1) * BK);
            CP_COMMIT();
            CP_WAIT(1);
        } else {
            CP_WAIT(0);
        }
        __syncthreads();

        #pragma unroll
        for (int s = 0; s < 2; s++) {          // two k16 steps in BK=32
            uint32_t a[2][4], bfr[8][2];
            #pragma unroll
            for (int mt = 0; mt < 2; mt++) {
                int row = a_row + mt * 16;
                LDM_X4(a[mt][0], a[mt][1], a[mt][2], a[mt][3],
                       smA[st] + swoff(row, a_chb + 2 * s));
            }
            #pragma unroll
            for (int p = 0; p < 4; p++) {      // each x4 covers ntiles 2p,2p+1
                int row = b_row + p * 16;
                uint32_t r0, r1, r2, r3;
                LDM_X4(r0, r1, r2, r3, smB[st] + swoff(row, b_chb + 2 * s));
                bfr[2 * p][0] = r0; bfr[2 * p][1] = r1;
                bfr[2 * p + 1][0] = r2; bfr[2 * p + 1][1] = r3;
            }
            #pragma unroll
            for (int mt = 0; mt < 2; mt++)
                #pragma unroll
                for (int nt = 0; nt < 8; nt++)
                    MMA16816(acc[mt][nt], a[mt], bfr[nt][0], bfr[nt][1]);
        }
        __syncthreads();
    }

    // ---- fused epilogue on register accumulators ----
    const bool diag = (bi == bj);
    float lsum = 0.0f;
    #pragma unroll
    for (int mt = 0; mt < 2; mt++) {
        const int rloc0 = warp_m * 32 + mt * 16 + (lane >> 2);
        #pragma unroll
        for (int half = 0; half < 2; half++) {
            const int rloc = rloc0 + half * 8;
            const float sqi = g_sq[i0 + rloc];
            const int   li  = g_lab[i0 + rloc];
            #pragma unroll
            for (int nt = 0; nt < 8; nt++) {
                const int cloc = warp_n * 64 + nt * 8 + (lane & 3) * 2;
                #pragma unroll
                for (int e = 0; e < 2; e++) {
                    const int jj = cloc + e;
                    if (!diag || rloc < jj) {
                        float g  = acc[mt][nt][half * 2 + e];
                        float d2 = fmaxf(sqi + s_sqj[jj] - 2.0f * g, 0.0f);
                        if (li == s_labj[jj]) {
                            lsum += 0.5f * sqrtf(d2);              // p = 1/512
                        } else if (d2 < RADIUS_F * RADIUS_F) {
                            lsum += 0.5f * (RADIUS_F - sqrtf(d2)); // ~never
                        }
                    }
                }
            }
        }
    }
    #pragma unroll
    for (int o = 16; o; o >>= 1) lsum += __shfl_xor_sync(0xffffffffu, lsum, o);
    if (lane == 0) atomicAdd(out, lsum * (1.0f / (float)B));
}

extern "C" void kernel_launch(void* const* d_in, const int* in_sizes, int n_in,
                              void* d_out, int out_size) {
    const float* f   = (const float*)d_in[0];
    const int*   lab = (const int*)d_in[1];   // int32 labels (JAX x64 off)
    float*       out = (float*)d_out;

    int B = in_sizes[1] / 3;

    cl_init_out<<<1, 1>>>(out);
    cl_prep<<<(B * 32 + 255) / 256, 256>>>(f, lab, B);

    dim3 grid(B / BN, B / BM);
    cl_pair_mma<<<grid, 256>>>(out, B);
}

// round 12
// speedup vs baseline: 3.6763x; 1.0653x over previous
#include <cuda_runtime.h>
#include <cuda_bf16.h>
#include <math.h>
#include <stdint.h>

// ContrastiveLoss B=4096, D=256, L=3.
// bf16 Gram via ldmatrix + mma.sync m16n8k16 (portable PTX; tcgen05 rejected
// by the harness's compute_103 lowering). R12: fold out-init into prep,
// triangular 528-CTA launch (no dead blocks), BK=64 (half the barriers).

#define RADIUS_F 1.0f
#define MAXB  4096
#define DFEAT 256
#define BM 128
#define BN 128
#define BK 64

__device__ float g_sq[MAXB];
__device__ int   g_lab[MAXB];
__device__ __align__(1024) __nv_bfloat16 g_fb[MAXB * DFEAT];  // row-major bf16

// one warp per row: exact fp32 norm, packed labels, bf16 row store; zero out[0]
__global__ void cl_prep(const float* __restrict__ f, const int* __restrict__ lab,
                        float* __restrict__ out, int B) {
    if (blockIdx.x == 0 && threadIdx.x == 0) out[0] = 0.0f;
    int row  = (blockIdx.x * blockDim.x + threadIdx.x) >> 5;
    int lane = threadIdx.x & 31;
    if (row >= B) return;
    const float* r = f + (size_t)row * DFEAT;

    float4 v0 = *reinterpret_cast<const float4*>(r + lane * 8);
    float4 v1 = *reinterpret_cast<const float4*>(r + lane * 8 + 4);
    float s = 0.0f;
    s = fmaf(v0.x, v0.x, s); s = fmaf(v0.y, v0.y, s);
    s = fmaf(v0.z, v0.z, s); s = fmaf(v0.w, v0.w, s);
    s = fmaf(v1.x, v1.x, s); s = fmaf(v1.y, v1.y, s);
    s = fmaf(v1.z, v1.z, s); s = fmaf(v1.w, v1.w, s);
    #pragma unroll
    for (int o = 16; o; o >>= 1) s += __shfl_xor_sync(0xffffffffu, s, o);
    if (lane == 0) {
        g_sq[row]  = s;
        g_lab[row] = lab[row * 3 + 0] | (lab[row * 3 + 1] << 3) | (lab[row * 3 + 2] << 6);
    }

    __nv_bfloat162 b0 = __float22bfloat162_rn(make_float2(v0.x, v0.y));
    __nv_bfloat162 b1 = __float22bfloat162_rn(make_float2(v0.z, v0.w));
    __nv_bfloat162 b2 = __float22bfloat162_rn(make_float2(v1.x, v1.y));
    __nv_bfloat162 b3 = __float22bfloat162_rn(make_float2(v1.z, v1.w));
    uint4 pk;
    pk.x = *reinterpret_cast<uint32_t*>(&b0);
    pk.y = *reinterpret_cast<uint32_t*>(&b1);
    pk.z = *reinterpret_cast<uint32_t*>(&b2);
    pk.w = *reinterpret_cast<uint32_t*>(&b3);
    *reinterpret_cast<uint4*>(g_fb + (size_t)row * DFEAT + lane * 8) = pk;
}

// ---- helpers ----
__device__ __forceinline__ uint32_t smem_u32(const void* p) {
    uint32_t a;
    asm("{ .reg .u64 t; cvta.to.shared.u64 t, %1; cvt.u32.u64 %0, t; }" : "=r"(a) : "l"(p));
    return a;
}
// tile row = 128 bytes (64 bf16) = 8x 16B chunks; XOR chunks by row&7
__device__ __forceinline__ uint32_t swoff(int row, int ch) {
    return (uint32_t)(row * 128 + (((ch) ^ (row & 7)) << 4));
}
#define CP_ASYNC16(smem, gptr) \
    asm volatile("cp.async.ca.shared.global [%0], [%1], 16;" :: "r"(smem), "l"(gptr) : "memory")
#define CP_COMMIT() asm volatile("cp.async.commit_group;" ::: "memory")
#define CP_WAIT(n)  asm volatile("cp.async.wait_group %0;" :: "n"(n) : "memory")
#define LDM_X4(r0, r1, r2, r3, a) \
    asm volatile("ldmatrix.sync.aligned.m8n8.x4.shared.b16 {%0,%1,%2,%3}, [%4];" \
                 : "=r"(r0), "=r"(r1), "=r"(r2), "=r"(r3) : "r"(a))
#define MMA16816(c, A, b0, b1) \
    asm volatile("mma.sync.aligned.m16n8k16.row.col.f32.bf16.bf16.f32 " \
                 "{%0,%1,%2,%3}, {%4,%5,%6,%7}, {%8,%9}, {%0,%1,%2,%3};" \
                 : "+f"((c)[0]), "+f"((c)[1]), "+f"((c)[2]), "+f"((c)[3]) \
                 : "r"((A)[0]), "r"((A)[1]), "r"((A)[2]), "r"((A)[3]), "r"(b0), "r"(b1))

#define TILE_BYTES (BM * BK * 2)          // 16KB per operand per stage
#define SM_SQJ  (4 * TILE_BYTES)          // after 2 stages x 2 ops = 64KB
#define SM_LABJ (SM_SQJ + 512)
#define SM_TOTAL (SM_LABJ + 512)

__global__ __launch_bounds__(256, 2)
void cl_pair_mma(float* __restrict__ out, int B, int NT) {
    // triangular tile index -> (bi, bj), bi <= bj
    const int t = blockIdx.x;
    const float tn2 = 2.0f * NT + 1.0f;
    int bi = (int)((tn2 - sqrtf(tn2 * tn2 - 8.0f * t)) * 0.5f);
    // fixup fp edges; start(bi) = bi*NT - bi*(bi-1)/2
    while ((bi + 1) * NT - ((bi + 1) * bi) / 2 <= t) bi++;
    while (bi * NT - (bi * (bi - 1)) / 2 > t) bi--;
    const int bj = bi + (t - (bi * NT - (bi * (bi - 1)) / 2));

    extern __shared__ __align__(16) char smem[];
    const uint32_t sbase = smem_u32(smem);
    float* s_sqj = (float*)(smem + SM_SQJ);
    int*   s_labj = (int*)(smem + SM_LABJ);

    const int tid    = threadIdx.x;
    const int lane   = tid & 31;
    const int wid    = tid >> 5;
    const int warp_m = wid & 3;
    const int warp_n = wid >> 2;
    const int i0 = bi * BM, j0 = bj * BN;

    const char* gA = reinterpret_cast<const char*>(g_fb + (size_t)i0 * DFEAT);
    const char* gB = reinterpret_cast<const char*>(g_fb + (size_t)j0 * DFEAT);
    // stage st, op o at offset (st*2+o)*16KB
    uint32_t smA[2] = { sbase, sbase + 2 * TILE_BYTES };
    uint32_t smB[2] = { sbase + TILE_BYTES, sbase + 3 * TILE_BYTES };

    // loader: 1024 chunks/op/stage; thread -> row tid>>1, chunks {0..3}|{4..7}
    const int lrow = tid >> 1;
    const int lchb = (tid & 1) * 4;
    auto load_stage = [&](int st, int k0) {
        const char* ga = gA + (size_t)lrow * (DFEAT * 2) + k0 * 2;
        const char* gb = gB + (size_t)lrow * (DFEAT * 2) + k0 * 2;
        #pragma unroll
        for (int c = 0; c < 4; c++) {
            int ch = lchb + c;
            CP_ASYNC16(smA[st] + swoff(lrow, ch), ga + ch * 16);
            CP_ASYNC16(smB[st] + swoff(lrow, ch), gb + ch * 16);
        }
    };

    if (tid < BN) {
        s_sqj[tid]  = g_sq[j0 + tid];
        s_labj[tid] = g_lab[j0 + tid];
    }

    float acc[2][8][4];
    #pragma unroll
    for (int mt = 0; mt < 2; mt++)
        #pragma unroll
        for (int nt = 0; nt < 8; nt++)
            #pragma unroll
            for (int e = 0; e < 4; e++) acc[mt][nt][e] = 0.0f;

    load_stage(0, 0);
    CP_COMMIT();

    const int a_row = warp_m * 32 + (lane & 15);                      // + mt*16
    const int a_chb = lane >> 4;                                      // 0/1
    const int b_row = warp_n * 64 + (lane & 7) + ((lane & 16) >> 1);  // + p*16
    const int b_chb = (lane >> 3) & 1;

    const int NK = DFEAT / BK;   // 4
    for (int kt = 0; kt < NK; kt++) {
        const int st = kt & 1;
        if (kt + 1 < NK) {
            load_stage(st ^ 1, (kt + 1) * BK);
            CP_COMMIT();
            CP_WAIT(1);
        } else {
            CP_WAIT(0);
        }
        __syncthreads();

        #pragma unroll
        for (int s = 0; s < 4; s++) {          // four k16 steps in BK=64
            uint32_t a[2][4], bfr[8][2];
            #pragma unroll
            for (int mt = 0; mt < 2; mt++) {
                int row = a_row + mt * 16;
                LDM_X4(a[mt][0], a[mt][1], a[mt][2], a[mt][3],
                       smA[st] + swoff(row, 2 * s + a_chb));
            }
            #pragma unroll
            for (int p = 0; p < 4; p++) {
                int row = b_row + p * 16;
                uint32_t r0, r1, r2, r3;
                LDM_X4(r0, r1, r2, r3, smB[st] + swoff(row, 2 * s + b_chb));
                bfr[2 * p][0] = r0; bfr[2 * p][1] = r1;
                bfr[2 * p + 1][0] = r2; bfr[2 * p + 1][1] = r3;
            }
            #pragma unroll
            for (int mt = 0; mt < 2; mt++)
                #pragma unroll
                for (int nt = 0; nt < 8; nt++)
                    MMA16816(acc[mt][nt], a[mt], bfr[nt][0], bfr[nt][1]);
        }
        __syncthreads();
    }

    // ---- fused epilogue on register accumulators ----
    const bool diag = (bi == bj);
    float lsum = 0.0f;
    #pragma unroll
    for (int mt = 0; mt < 2; mt++) {
        const int rloc0 = warp_m * 32 + mt * 16 + (lane >> 2);
        #pragma unroll
        for (int half = 0; half < 2; half++) {
            const int rloc = rloc0 + half * 8;
            const float sqi = g_sq[i0 + rloc];
            const int   li  = g_lab[i0 + rloc];
            #pragma unroll
            for (int nt = 0; nt < 8; nt++) {
                const int cloc = warp_n * 64 + nt * 8 + (lane & 3) * 2;
                #pragma unroll
                for (int e = 0; e < 2; e++) {
                    const int jj = cloc + e;
                    if (!diag || rloc < jj) {
                        float g  = acc[mt][nt][half * 2 + e];
                        float d2 = fmaxf(sqi + s_sqj[jj] - 2.0f * g, 0.0f);
                        if (li == s_labj[jj]) {
                            lsum += 0.5f * sqrtf(d2);              // p = 1/512
                        } else if (d2 < RADIUS_F * RADIUS_F) {
                            lsum += 0.5f * (RADIUS_F - sqrtf(d2)); // ~never
                        }
                    }
                }
            }
        }
    }
    #pragma unroll
    for (int o = 16; o; o >>= 1) lsum += __shfl_xor_sync(0xffffffffu, lsum, o);
    if (lane == 0) atomicAdd(out, lsum * (1.0f / (float)B));
}

extern "C" void kernel_launch(void* const* d_in, const int* in_sizes, int n_in,
                              void* d_out, int out_size) {
    const float* f   = (const float*)d_in[0];
    const int*   lab = (const int*)d_in[1];   // int32 labels (JAX x64 off)
    float*       out = (float*)d_out;

    int B  = in_sizes[1] / 3;
    int NT = B / BM;                           // 32
    int ntiles = NT * (NT + 1) / 2;            // 528

    cudaFuncSetAttribute(cl_pair_mma, cudaFuncAttributeMaxDynamicSharedMemorySize, SM_TOTAL);

    cl_prep<<<(B * 32 + 255) / 256, 256>>>(f, lab, out, B);
    cl_pair_mma<<<ntiles, 256, SM_TOTAL>>>(out, B, NT);
}